// round 15
// baseline (speedup 1.0000x reference)
#include <cuda_runtime.h>
#include <cuda_fp16.h>
#include <math.h>
#include <stdint.h>

// Problem constants
#define BB 4
#define SS 512
#define DD 1024
#define HH 16
#define DHH 64
#define DFF 4096
#define LL 6
#define MTOK (BB*SS)          // 2048 token rows

typedef __half fp16;

// ================= device scratch =================
__device__ float g_x  [MTOK*DD];
__device__ fp16  g_xh [MTOK*DD];
__device__ fp16  g_qh [MTOK*DD],  g_ql [MTOK*DD];   // Q fp16 split [B,H,S,64] (scores accuracy)
__device__ fp16  g_kh [MTOK*DD];                    // K fp16 [B,H,S,64]
__device__ float g_v  [MTOK*DD];                    // V fp32 [B,H,S,64]
__device__ fp16  g_avh[MTOK*DD];
__device__ float g_y  [MTOK*DD];
__device__ float g_x1 [MTOK*DD];
__device__ fp16  g_x1h[MTOK*DD];
__device__ fp16  g_ffh[MTOK*DFF];

__device__ fp16 g_wqkvT[3*LL*DD*DD];   // [3][L][N][K]
__device__ fp16 g_woT[LL*DD*DD];
__device__ fp16 g_w1T[LL*DD*DFF];
__device__ fp16 g_w2T[LL*DFF*DD];
__device__ float g_bqkv[3*LL*DD];

// ================= helpers =================
__device__ __forceinline__ uint32_t smem_u32(const void* p) {
    uint32_t a;
    asm("{ .reg .u64 t; cvta.to.shared.u64 t, %1; cvt.u32.u64 %0, t; }" : "=r"(a) : "l"(p));
    return a;
}
__device__ __forceinline__ void split_fp16(float v, fp16& h, fp16& l) {
    h = __float2half_rn(v);
    l = __float2half_rn(v - __half2float(h));
}

#define CP_ASYNC16(sa, ga) \
    asm volatile("cp.async.cg.shared.global [%0], [%1], 16;" :: "r"(sa), "l"(ga) : "memory")
#define CP_COMMIT() asm volatile("cp.async.commit_group;" ::: "memory")
#define CP_WAIT1()  asm volatile("cp.async.wait_group 1;" ::: "memory")

#define LDSM_X4(r0,r1,r2,r3, addr) \
    asm volatile("ldmatrix.sync.aligned.m8n8.x4.shared.b16 {%0,%1,%2,%3}, [%4];" \
        : "=r"(r0), "=r"(r1), "=r"(r2), "=r"(r3) : "r"(addr))

#define MMA_F16(d, a, b0, b1) \
    asm volatile("mma.sync.aligned.m16n8k16.row.col.f32.f16.f16.f32 " \
        "{%0,%1,%2,%3}, {%4,%5,%6,%7}, {%8,%9}, {%0,%1,%2,%3};" \
        : "+f"((d)[0]), "+f"((d)[1]), "+f"((d)[2]), "+f"((d)[3]) \
        : "r"((a)[0]), "r"((a)[1]), "r"((a)[2]), "r"((a)[3]), "r"(b0), "r"(b1))

// ================= embedding =================
__global__ void embed_kernel(const int* __restrict__ tok,
                             const float* __restrict__ we,
                             const float* __restrict__ pt,
                             float* __restrict__ x,
                             fp16* __restrict__ xh)
{
    int m = blockIdx.x;
    int t = tok[m];
    const float* wr = we + (size_t)t * DD;
    const float* pr = pt + (size_t)t * DD;
    size_t base = (size_t)m * DD;
    for (int j = threadIdx.x; j < DD; j += blockDim.x) {
        float v = wr[j] + pr[j];
        x[base + j] = v;
        xh[base + j] = __float2half_rn(v);
    }
}

// ========== weight transpose + fp16 round ==========
__global__ __launch_bounds__(256)
void wsplit_kernel(const float* __restrict__ W, fp16* __restrict__ Th, int K, int N)
{
    __shared__ float s[32][33];
    int nb = blockIdx.x * 32, kb = blockIdx.y * 32;
    int tx = threadIdx.x & 31, ty = threadIdx.x >> 5;
    #pragma unroll
    for (int j = 0; j < 4; j++)
        s[ty + 8*j][tx] = W[(size_t)(kb + ty + 8*j) * N + nb + tx];
    __syncthreads();
    #pragma unroll
    for (int j = 0; j < 4; j++) {
        float v = s[tx][ty + 8*j];
        Th[(size_t)(nb + ty + 8*j) * K + kb + tx] = __float2half_rn(v);
    }
}

__global__ void bcat_kernel(const float* __restrict__ a, const float* __restrict__ b,
                            const float* __restrict__ c, float* __restrict__ dst, int n)
{
    int i = blockIdx.x * blockDim.x + threadIdx.x;
    if (i < n) { dst[i] = a[i]; dst[n + i] = b[i]; dst[2*n + i] = c[i]; }
}

// ================= fp16 mma.sync GEMM: BM=64, BK=64, 3-stage distance-2 =================
// BN in {128,64}; BN=128 runs 3 CTAs/SM, BN=64 runs 4.
// mode 0: fp32+bias; 1: relu->fp16; 2: +bias+Res->fp32;
// mode 3: QKV: z=0 -> qh/ql fp16 split remap, z=1 -> Khp fp16 remap, z=2 -> C fp32 remap.
template<int BN>
__global__ __launch_bounds__(256, (BN == 64) ? 4 : 3)
void gemm_kernel(const fp16* __restrict__ Ah,
                 const fp16* __restrict__ Bh_,
                 const float* __restrict__ bias_, const float* __restrict__ Res,
                 float* __restrict__ C_, fp16* __restrict__ Ch, fp16* __restrict__ Cl,
                 fp16* __restrict__ Khp,
                 int K, int N, int mode, size_t zsB, size_t zsBias)
{
    constexpr int BM = 64;
    constexpr int SA = BM * 128;            // A bytes per stage (64 rows x 64 fp16)
    constexpr int SB = BN * 128;            // B bytes per stage
    constexpr int STAGE = SA + SB;
    constexpr int MT  = (BN == 128) ? 2 : 1;   // m16 tiles per warp
    constexpr int NPn = 2;                     // ldsm-B tiles per warp (16 n each)

    extern __shared__ char smem[];
    const uint32_t sb = smem_u32(smem);
    const int tid = threadIdx.x;
    const int lane = tid & 31, wid = tid >> 5;
    const int WM = (BN == 128) ? (wid & 1) : (wid & 3);
    const int WN = (BN == 128) ? (wid >> 1) : (wid >> 2);
    const int m0 = blockIdx.y * BM, n0 = blockIdx.x * BN;

    const fp16* Bh = Bh_ + blockIdx.z * zsB;
    const float* bias = bias_ + blockIdx.z * zsBias;

    const int lrow = tid >> 3, lkg = tid & 7;
    const uint32_t so = (uint32_t)(lrow * 128 + ((lkg ^ (lrow & 7)) << 4));
    const fp16* gAh0 = Ah + (size_t)(m0 + lrow) * K + lkg * 8;
    const fp16* gBh0 = Bh + (size_t)(n0 + lrow) * K + lkg * 8;

    int matA = lane >> 3;
    int arow_local = ((matA & 1) << 3) + (lane & 7);
    int akgbit = matA >> 1;
    uint32_t offA[MT][4];
    #pragma unroll
    for (int mt = 0; mt < MT; mt++) {
        int row = WM * (MT * 16) + mt * 16 + arow_local;
        #pragma unroll
        for (int ks = 0; ks < 4; ks++)
            offA[mt][ks] = (uint32_t)(row * 128 + (((ks * 2 + akgbit) ^ (row & 7)) << 4));
    }
    int brow_local = ((matA >> 1) << 3) + (lane & 7);
    int bkgbit = matA & 1;
    uint32_t offB[NPn][4];
    #pragma unroll
    for (int np = 0; np < NPn; np++) {
        int row = WN * (NPn * 16) + np * 16 + brow_local;
        #pragma unroll
        for (int ks = 0; ks < 4; ks++)
            offB[np][ks] = (uint32_t)(row * 128 + (((ks * 2 + bkgbit) ^ (row & 7)) << 4));
    }

    float acc[MT][2*NPn][4];
    #pragma unroll
    for (int i = 0; i < MT; i++)
        #pragma unroll
        for (int j = 0; j < 2*NPn; j++)
            #pragma unroll
            for (int qq = 0; qq < 4; qq++) acc[i][j][qq] = 0.f;

    const int NC = K >> 6;

    auto load_stage = [&](int stage, int chunk) {
        uint32_t base = sb + stage * STAGE;
        size_t gk = (size_t)(chunk << 6);
        #pragma unroll
        for (int t = 0; t < BM/32; t++)
            CP_ASYNC16(base      + so + 4096u*t, gAh0 + (size_t)(32*t) * K + gk);
        #pragma unroll
        for (int t = 0; t < BN/32; t++)
            CP_ASYNC16(base + SA + so + 4096u*t, gBh0 + (size_t)(32*t) * K + gk);
    };

    load_stage(0, 0); CP_COMMIT();
    if (NC > 1) load_stage(1, 1);
    CP_COMMIT();

    int cur = 0;
    for (int i = 0; i < NC; i++) {
        CP_WAIT1();
        __syncthreads();

        uint32_t base = sb + cur * STAGE;
        uint32_t sAh = base, sBh = base + SA;

        #pragma unroll
        for (int ks = 0; ks < 4; ks++) {
            uint32_t ah[MT][4];
            #pragma unroll
            for (int mt = 0; mt < MT; mt++)
                LDSM_X4(ah[mt][0], ah[mt][1], ah[mt][2], ah[mt][3], sAh + offA[mt][ks]);
            #pragma unroll
            for (int np = 0; np < NPn; np++) {
                uint32_t bh[4];
                LDSM_X4(bh[0], bh[1], bh[2], bh[3], sBh + offB[np][ks]);
                #pragma unroll
                for (int mt = 0; mt < MT; mt++) {
                    MMA_F16(acc[mt][np*2+0], ah[mt], bh[0], bh[1]);
                    MMA_F16(acc[mt][np*2+1], ah[mt], bh[2], bh[3]);
                }
            }
        }
        __syncthreads();
        if (i + 2 < NC) {
            int pf = cur + 2; if (pf >= 3) pf -= 3;
            load_stage(pf, i + 2);
        }
        CP_COMMIT();
        cur = (cur + 1 == 3) ? 0 : cur + 1;
    }

    // -------- epilogue --------
    #pragma unroll
    for (int mt = 0; mt < MT; mt++) {
        int r0 = m0 + WM * (MT * 16) + mt * 16 + (lane >> 2);
        int r1 = r0 + 8;
        #pragma unroll
        for (int nt = 0; nt < 2*NPn; nt++) {
            int c = n0 + WN * (NPn * 16) + nt * 8 + ((lane & 3) << 1);
            float2 bv = *(const float2*)(bias + c);
            float v00 = acc[mt][nt][0] + bv.x, v01 = acc[mt][nt][1] + bv.y;
            float v10 = acc[mt][nt][2] + bv.x, v11 = acc[mt][nt][3] + bv.y;
            if (mode == 0) {
                *(float2*)(C_ + (size_t)r0 * N + c) = make_float2(v00, v01);
                *(float2*)(C_ + (size_t)r1 * N + c) = make_float2(v10, v11);
            } else if (mode == 1) {
                v00 = fmaxf(v00, 0.f); v01 = fmaxf(v01, 0.f);
                v10 = fmaxf(v10, 0.f); v11 = fmaxf(v11, 0.f);
                *(__half2*)(Ch + (size_t)r0 * N + c) =
                    __halves2half2(__float2half_rn(v00), __float2half_rn(v01));
                *(__half2*)(Ch + (size_t)r1 * N + c) =
                    __halves2half2(__float2half_rn(v10), __float2half_rn(v11));
            } else if (mode == 2) {
                float2 q0 = *(const float2*)(Res + (size_t)r0 * N + c);
                float2 q1 = *(const float2*)(Res + (size_t)r1 * N + c);
                *(float2*)(C_ + (size_t)r0 * N + c) = make_float2(v00 + q0.x, v01 + q0.y);
                *(float2*)(C_ + (size_t)r1 * N + c) = make_float2(v10 + q1.x, v11 + q1.y);
            } else {
                int b0_ = r0 >> 9, s0_ = r0 & 511;
                int b1_ = r1 >> 9, s1_ = r1 & 511;
                int h_ = c >> 6, d_ = c & 63;
                size_t i0 = ((((size_t)b0_ * HH + h_) * SS + s0_) << 6) + d_;
                size_t i1 = ((((size_t)b1_ * HH + h_) * SS + s1_) << 6) + d_;
                int z = blockIdx.z;
                if (z == 0) {
                    fp16 h0,l0,h1,l1,h2,l2,h3,l3;
                    split_fp16(v00,h0,l0); split_fp16(v01,h1,l1);
                    split_fp16(v10,h2,l2); split_fp16(v11,h3,l3);
                    *(__half2*)(Ch + i0) = __halves2half2(h0, h1);
                    *(__half2*)(Cl + i0) = __halves2half2(l0, l1);
                    *(__half2*)(Ch + i1) = __halves2half2(h2, h3);
                    *(__half2*)(Cl + i1) = __halves2half2(l2, l3);
                } else if (z == 1) {
                    *(__half2*)(Khp + i0) = __halves2half2(__float2half_rn(v00), __float2half_rn(v01));
                    *(__half2*)(Khp + i1) = __halves2half2(__float2half_rn(v10), __float2half_rn(v11));
                } else {
                    *(float2*)(C_ + i0) = make_float2(v00, v01);
                    *(float2*)(C_ + i1) = make_float2(v10, v11);
                }
            }
        }
    }
}

// ================= fused attention: tensor-core scores + fp32 softmax/AV =================
#define SC_B   0
#define RA_B   (32*513*4)              // 65664
#define RB_B   (RA_B + 24576)          // 90240
#define ATT_SMEM (RB_B + 17408)        // 107648

__global__ __launch_bounds__(256, 2)
void attn_kernel(const fp16* __restrict__ qh, const fp16* __restrict__ ql,
                 const fp16* __restrict__ kh, const float* __restrict__ v,
                 const int* __restrict__ tok,
                 float* __restrict__ probs, fp16* __restrict__ avh)
{
    extern __shared__ char smc[];
    float* sm = (float*)smc;
    float* sc = sm;                        // 32 x 513
    const uint32_t sb = smem_u32(smc);
    int qb = blockIdx.x, h = blockIdx.y, b = blockIdx.z;
    int tid = threadIdx.x;
    int w = tid >> 5, lane = tid & 31;

    const size_t bh_off = (((size_t)b * HH + h) * SS) << 6;
    const fp16* qh_g = qh + bh_off + ((size_t)qb * 32 << 6);
    const fp16* ql_g = ql + bh_off + ((size_t)qb * 32 << 6);
    const fp16* kh_g = kh + bh_off;
    const float* v_g = v + bh_off;
    const int* tb = tok + b * SS;

    auto pf_k = [&](int ch, int buf) {
        uint32_t sdst = sb + RA_B + 8192 + buf * 8192;
        const fp16* src = kh_g + (size_t)(ch * 64) * 64;
        #pragma unroll
        for (int t = 0; t < 2; t++) {
            int j = tid + 256 * t;
            int row = j >> 3, kg = j & 7;
            CP_ASYNC16(sdst + (uint32_t)(row * 128 + ((kg ^ (row & 7)) << 4)),
                       src + (size_t)row * 64 + kg * 8);
        }
    };
    {
        int row = tid >> 3, kg = tid & 7;
        uint32_t so = (uint32_t)(row * 128 + ((kg ^ (row & 7)) << 4));
        CP_ASYNC16(sb + RA_B + so,        qh_g + (size_t)row * 64 + kg * 8);
        CP_ASYNC16(sb + RA_B + 4096 + so, ql_g + (size_t)row * 64 + kg * 8);
    }
    pf_k(0, 0);
    CP_COMMIT();

    int qh16 = (w >> 2) * 16;
    int keyq = w & 3;
    int matA = lane >> 3;
    int arow = qh16 + ((matA & 1) << 3) + (lane & 7);
    int akg = matA >> 1;
    uint32_t offQ[4];
    #pragma unroll
    for (int ks = 0; ks < 4; ks++)
        offQ[ks] = (uint32_t)(arow * 128 + (((ks * 2 + akg) ^ (arow & 7)) << 4));
    int brow = keyq * 16 + ((matA >> 1) << 3) + (lane & 7);
    int bkg = matA & 1;
    uint32_t offK[4];
    #pragma unroll
    for (int ks = 0; ks < 4; ks++)
        offK[ks] = (uint32_t)(brow * 128 + (((ks * 2 + bkg) ^ (brow & 7)) << 4));

    const uint32_t qhb = sb + RA_B, qlb = sb + RA_B + 4096;

    for (int ch = 0; ch < 8; ch++) {
        if (ch < 7) pf_k(ch + 1, (ch + 1) & 1);
        CP_COMMIT();
        CP_WAIT1();
        __syncthreads();
        uint32_t kb = sb + RA_B + 8192 + (ch & 1) * 8192;

        float c0[4] = {0.f,0.f,0.f,0.f}, c1[4] = {0.f,0.f,0.f,0.f};
        #pragma unroll
        for (int ks = 0; ks < 4; ks++) {
            uint32_t ah[4], al[4], bbv[4];
            LDSM_X4(ah[0], ah[1], ah[2], ah[3], qhb + offQ[ks]);
            LDSM_X4(al[0], al[1], al[2], al[3], qlb + offQ[ks]);
            LDSM_X4(bbv[0], bbv[1], bbv[2], bbv[3], kb + offK[ks]);
            MMA_F16(c0, ah, bbv[0], bbv[1]);
            MMA_F16(c0, al, bbv[0], bbv[1]);
            MMA_F16(c1, ah, bbv[2], bbv[3]);
            MMA_F16(c1, al, bbv[2], bbv[3]);
        }
        int tc = lane >> 2, tcol = (lane & 3) * 2;
        int q0 = qh16 + tc, q1 = q0 + 8;
        #pragma unroll
        for (int nt = 0; nt < 2; nt++) {
            float* cc = nt ? c1 : c0;
            int key0 = ch * 64 + keyq * 16 + nt * 8 + tcol;
            bool m0 = (tb[key0] == 0), m1 = (tb[key0 + 1] == 0);
            sc[q0 * 513 + key0]     = m0 ? -INFINITY : cc[0] * 0.125f;
            sc[q0 * 513 + key0 + 1] = m1 ? -INFINITY : cc[1] * 0.125f;
            sc[q1 * 513 + key0]     = m0 ? -INFINITY : cc[2] * 0.125f;
            sc[q1 * 513 + key0 + 1] = m1 ? -INFINITY : cc[3] * 0.125f;
        }
        __syncthreads();
    }

    auto pf_v = [&](const float* gsrc, int buf) {
        uint32_t sdst = sb + (buf ? RB_B : RA_B);
        #pragma unroll
        for (int t = 0; t < 4; t++) {
            int j = tid + 256 * t;
            int row = j >> 4, c4 = j & 15;
            CP_ASYNC16(sdst + (uint32_t)(row * 68 + c4 * 4) * 4,
                       gsrc + (size_t)row * 64 + c4 * 4);
        }
    };
    pf_v(v_g, 0); CP_COMMIT();

    #pragma unroll 1
    for (int rr = 0; rr < 4; rr++) {
        int row = w * 4 + rr;
        float* srow = sc + row * 513;
        float m = -INFINITY;
        for (int j = lane; j < 512; j += 32) m = fmaxf(m, srow[j]);
        #pragma unroll
        for (int o = 16; o > 0; o >>= 1) m = fmaxf(m, __shfl_xor_sync(~0u, m, o));
        float sum = 0.f;
        for (int j = lane; j < 512; j += 32) {
            float e = __expf(srow[j] - m);
            srow[j] = e; sum += e;
        }
        #pragma unroll
        for (int o = 16; o > 0; o >>= 1) sum += __shfl_xor_sync(~0u, sum, o);
        float inv = 1.f / sum;
        float* prow = probs + ((((size_t)b * HH + h) * SS + qb * 32 + row) << 9);
        for (int j = lane; j < 512; j += 32) {
            float p = srow[j] * inv;
            srow[j] = p;
            prow[j] = p;
        }
    }
    __syncthreads();

    int ql_ = tid & 31, dg = tid >> 5;
    float a8[8] = {};
    for (int ch = 0; ch < 8; ch++) {
        if (ch < 7) pf_v(v_g + (size_t)(ch + 1) * 64 * 64, (ch + 1) & 1);
        CP_COMMIT();
        CP_WAIT1();
        __syncthreads();
        const float* kvb = sm + ((ch & 1) ? (RB_B >> 2) : (RA_B >> 2));
        const float* srow = sc + ql_ * 513 + ch * 64;
        #pragma unroll 4
        for (int kk = 0; kk < 64; kk++) {
            float s = srow[kk];
            float4 v0 = *(const float4*)(kvb + kk * 68 + dg * 8);
            float4 v1 = *(const float4*)(kvb + kk * 68 + dg * 8 + 4);
            a8[0] = fmaf(s, v0.x, a8[0]); a8[1] = fmaf(s, v0.y, a8[1]);
            a8[2] = fmaf(s, v0.z, a8[2]); a8[3] = fmaf(s, v0.w, a8[3]);
            a8[4] = fmaf(s, v1.x, a8[4]); a8[5] = fmaf(s, v1.y, a8[5]);
            a8[6] = fmaf(s, v1.z, a8[6]); a8[7] = fmaf(s, v1.w, a8[7]);
        }
        __syncthreads();
    }
    size_t o = ((size_t)(b * SS + qb * 32 + ql_) << 10) + h * 64 + dg * 8;
    uint32_t ph[4];
    #pragma unroll
    for (int i = 0; i < 4; i++) {
        ph[i] = ((uint32_t)__half_as_ushort(__float2half_rn(a8[2*i+1])) << 16)
              | __half_as_ushort(__float2half_rn(a8[2*i]));
    }
    *(uint4*)(avh + o) = make_uint4(ph[0], ph[1], ph[2], ph[3]);
}

// ================= layernorm + fp16 =================
__global__ __launch_bounds__(256)
void ln_kernel(const float* __restrict__ in, float* __restrict__ out,
               fp16* __restrict__ oh)
{
    int row = blockIdx.x;
    int tid = threadIdx.x;
    const float* r = in + (size_t)row * DD;
    float v0 = r[tid], v1 = r[tid + 256], v2 = r[tid + 512], v3 = r[tid + 768];
    float s = v0 + v1 + v2 + v3;

    __shared__ float sh[32];
    #pragma unroll
    for (int o = 16; o > 0; o >>= 1) s += __shfl_down_sync(~0u, s, o);
    if ((tid & 31) == 0) sh[tid >> 5] = s;
    __syncthreads();
    if (tid < 8) {
        s = sh[tid];
        #pragma unroll
        for (int o = 4; o > 0; o >>= 1) s += __shfl_down_sync(0xffu, s, o);
        if (tid == 0) sh[0] = s;
    }
    __syncthreads();
    float mean = sh[0] * (1.f / 1024.f);
    float d0 = v0 - mean, d1 = v1 - mean, d2 = v2 - mean, d3 = v3 - mean;
    float qv = d0*d0 + d1*d1 + d2*d2 + d3*d3;
    __syncthreads();
    #pragma unroll
    for (int o = 16; o > 0; o >>= 1) qv += __shfl_down_sync(~0u, qv, o);
    if ((tid & 31) == 0) sh[tid >> 5] = qv;
    __syncthreads();
    if (tid < 8) {
        qv = sh[tid];
        #pragma unroll
        for (int o = 4; o > 0; o >>= 1) qv += __shfl_down_sync(0xffu, qv, o);
        if (tid == 0) sh[0] = qv;
    }
    __syncthreads();
    float inv = rsqrtf(sh[0] * (1.f / 1024.f) + 1e-5f);
    size_t base = (size_t)row * DD;
    #pragma unroll
    for (int jj = 0; jj < 4; jj++) {
        float d = (jj == 0 ? d0 : jj == 1 ? d1 : jj == 2 ? d2 : d3);
        float val = d * inv;
        int idx = tid + jj * 256;
        out[base + idx] = val;
        oh[base + idx] = __float2half_rn(val);
    }
}

// ================= host driver =================
extern "C" void kernel_launch(void* const* d_in, const int* in_sizes, int n_in,
                              void* d_out, int out_size)
{
    const int*   tok = (const int*)d_in[0];
    const float* we  = (const float*)d_in[1];
    const float* pt  = (const float*)d_in[2];
    const float* Wq  = (const float*)d_in[3];  const float* bq = (const float*)d_in[4];
    const float* Wk  = (const float*)d_in[5];  const float* bk = (const float*)d_in[6];
    const float* Wv  = (const float*)d_in[7];  const float* bv = (const float*)d_in[8];
    const float* Wo  = (const float*)d_in[9];  const float* bo = (const float*)d_in[10];
    const float* W1  = (const float*)d_in[11]; const float* b1 = (const float*)d_in[12];
    const float* W2  = (const float*)d_in[13]; const float* b2 = (const float*)d_in[14];
    float* out = (float*)d_out;

    float *x, *yp, *x1p, *bqkv, *vf;
    fp16 *xh, *qhp, *qlp, *khp, *avh, *x1h, *ffh;
    cudaGetSymbolAddress((void**)&x,   g_x);
    cudaGetSymbolAddress((void**)&xh,  g_xh);
    cudaGetSymbolAddress((void**)&qhp, g_qh);  cudaGetSymbolAddress((void**)&qlp, g_ql);
    cudaGetSymbolAddress((void**)&khp, g_kh);  cudaGetSymbolAddress((void**)&vf,  g_v);
    cudaGetSymbolAddress((void**)&avh, g_avh);
    cudaGetSymbolAddress((void**)&yp,  g_y);
    cudaGetSymbolAddress((void**)&x1p, g_x1);
    cudaGetSymbolAddress((void**)&x1h, g_x1h);
    cudaGetSymbolAddress((void**)&ffh, g_ffh);
    cudaGetSymbolAddress((void**)&bqkv, g_bqkv);

    fp16 *wqkvT, *woT, *w1T, *w2T;
    cudaGetSymbolAddress((void**)&wqkvT, g_wqkvT);
    cudaGetSymbolAddress((void**)&woT, g_woT);
    cudaGetSymbolAddress((void**)&w1T, g_w1T);
    cudaGetSymbolAddress((void**)&w2T, g_w2T);

    const int GS_B128 = 3 * (64 * 128 + 128 * 128);   // 73728
    const int GS_B64  = 3 * (64 * 128 + 64 * 128);    // 49152
    cudaFuncSetAttribute(gemm_kernel<128>, cudaFuncAttributeMaxDynamicSharedMemorySize, GS_B128);
    cudaFuncSetAttribute(gemm_kernel<64>,  cudaFuncAttributeMaxDynamicSharedMemorySize, GS_B64);
    cudaFuncSetAttribute(attn_kernel, cudaFuncAttributeMaxDynamicSharedMemorySize, ATT_SMEM);

    static cudaStream_t s2 = nullptr;
    static cudaEvent_t eFork = nullptr, eLay[LL];
    if (!s2) {
        cudaStreamCreate(&s2);
        cudaEventCreateWithFlags(&eFork, cudaEventDisableTiming);
        for (int l = 0; l < LL; l++) cudaEventCreateWithFlags(&eLay[l], cudaEventDisableTiming);
    }

    const size_t PROJ = (size_t)DD * DD;
    const size_t WQKV = (size_t)LL * DD * DD;
    const size_t W1SZ = (size_t)DD * DFF;
    const size_t W2SZ = (size_t)DFF * DD;
    const size_t CORR = (size_t)BB * HH * SS * SS;

    auto split_layer = [&](int l, cudaStream_t st) {
        dim3 gP(DD/32, DD/32);
        wsplit_kernel<<<gP, 256, 0, st>>>(Wq + l*PROJ, wqkvT + l*PROJ,          DD, DD);
        wsplit_kernel<<<gP, 256, 0, st>>>(Wk + l*PROJ, wqkvT + WQKV + l*PROJ,   DD, DD);
        wsplit_kernel<<<gP, 256, 0, st>>>(Wv + l*PROJ, wqkvT + 2*WQKV + l*PROJ, DD, DD);
        wsplit_kernel<<<gP, 256, 0, st>>>(Wo + l*PROJ, woT + l*PROJ, DD, DD);
        dim3 g1(DFF/32, DD/32);
        wsplit_kernel<<<g1, 256, 0, st>>>(W1 + l*W1SZ, w1T + l*W1SZ, DD, DFF);
        dim3 g2(DD/32, DFF/32);
        wsplit_kernel<<<g2, 256, 0, st>>>(W2 + l*W2SZ, w2T + l*W2SZ, DFF, DD);
    };

    bcat_kernel<<<(LL*DD + 255)/256, 256>>>(bq, bk, bv, bqkv, LL*DD);
    split_layer(0, (cudaStream_t)0);
    embed_kernel<<<MTOK, 256>>>(tok, we, pt, x, xh);

    cudaEventRecord(eFork, (cudaStream_t)0);
    cudaStreamWaitEvent(s2, eFork, 0);
    for (int l = 1; l < LL; l++) {
        split_layer(l, s2);
        cudaEventRecord(eLay[l], s2);
    }

    dim3 gQKV(DD / 128, MTOK / 64, 3);    // (8,32,3) = 768 CTAs, BN=128
    dim3 gFF (DFF / 128, MTOK / 64);      // (32,32) = 1024 CTAs, BN=128
    dim3 gD64(DD / 64, MTOK / 64);        // (16,32) = 512 CTAs, BN=64
    dim3 gA  (SS / 32, HH, BB);           // (16,16,4)

    for (int l = 0; l < LL; l++) {
        if (l > 0) cudaStreamWaitEvent((cudaStream_t)0, eLay[l], 0);

        gemm_kernel<128><<<gQKV, 256, GS_B128>>>(xh, wqkvT + l*PROJ,
                                          bqkv + l*DD, nullptr, vf, qhp, qlp, khp,
                                          DD, DD, 3, WQKV, (size_t)LL*DD);

        float* probs_l = out + (size_t)MTOK * DD + (size_t)l * CORR;
        attn_kernel<<<gA, 256, ATT_SMEM>>>(qhp, qlp, khp, vf, tok, probs_l, avh);

        gemm_kernel<64><<<gD64, 256, GS_B64>>>(avh, woT + l*PROJ, bo + l*DD,
                                        x, yp, nullptr, nullptr, nullptr, DD, DD, 2, 0, 0);
        ln_kernel<<<MTOK, 256>>>(yp, x1p, x1h);

        gemm_kernel<128><<<gFF, 256, GS_B128>>>(x1h, w1T + l*W1SZ, b1 + l*DFF,
                                         nullptr, nullptr, ffh, nullptr, nullptr, DD, DFF, 1, 0, 0);
        gemm_kernel<64><<<gD64, 256, GS_B64>>>(ffh, w2T + l*W2SZ, b2 + l*DD,
                                        x1p, yp, nullptr, nullptr, nullptr, DFF, DD, 2, 0, 0);

        float* xdst = (l == LL - 1) ? out : x;
        ln_kernel<<<MTOK, 256>>>(yp, xdst, xh);
    }
}

// round 16
// speedup vs baseline: 1.0707x; 1.0707x over previous
#include <cuda_runtime.h>
#include <cuda_fp16.h>
#include <math.h>
#include <stdint.h>

// Problem constants
#define BB 4
#define SS 512
#define DD 1024
#define HH 16
#define DHH 64
#define DFF 4096
#define LL 6
#define MTOK (BB*SS)          // 2048 token rows

typedef __half fp16;

// ================= device scratch =================
__device__ float g_x  [MTOK*DD];
__device__ fp16  g_xh [MTOK*DD];
__device__ fp16  g_qh [MTOK*DD],  g_ql [MTOK*DD];   // Q fp16 split [B,H,S,64]
__device__ fp16  g_kh [MTOK*DD];                    // K fp16 [B,H,S,64]
__device__ float g_v  [MTOK*DD];                    // V fp32 [B,H,S,64]
__device__ fp16  g_avh[MTOK*DD];
__device__ float g_x1 [MTOK*DD];
__device__ fp16  g_x1h[MTOK*DD];
__device__ fp16  g_ffh[MTOK*DFF];
__device__ float g_part[2*MTOK*DD];                 // split-K partials

__device__ fp16 g_wqkvT[3*LL*DD*DD];   // [3][L][N][K]
__device__ fp16 g_woT[LL*DD*DD];
__device__ fp16 g_w1T[LL*DD*DFF];
__device__ fp16 g_w2T[LL*DFF*DD];
__device__ float g_bqkv[3*LL*DD];

// ================= helpers =================
__device__ __forceinline__ uint32_t smem_u32(const void* p) {
    uint32_t a;
    asm("{ .reg .u64 t; cvta.to.shared.u64 t, %1; cvt.u32.u64 %0, t; }" : "=r"(a) : "l"(p));
    return a;
}
__device__ __forceinline__ void split_fp16(float v, fp16& h, fp16& l) {
    h = __float2half_rn(v);
    l = __float2half_rn(v - __half2float(h));
}

#define CP_ASYNC16(sa, ga) \
    asm volatile("cp.async.cg.shared.global [%0], [%1], 16;" :: "r"(sa), "l"(ga) : "memory")
#define CP_COMMIT() asm volatile("cp.async.commit_group;" ::: "memory")
#define CP_WAIT1()  asm volatile("cp.async.wait_group 1;" ::: "memory")

#define LDSM_X4(r0,r1,r2,r3, addr) \
    asm volatile("ldmatrix.sync.aligned.m8n8.x4.shared.b16 {%0,%1,%2,%3}, [%4];" \
        : "=r"(r0), "=r"(r1), "=r"(r2), "=r"(r3) : "r"(addr))

#define MMA_F16(d, a, b0, b1) \
    asm volatile("mma.sync.aligned.m16n8k16.row.col.f32.f16.f16.f32 " \
        "{%0,%1,%2,%3}, {%4,%5,%6,%7}, {%8,%9}, {%0,%1,%2,%3};" \
        : "+f"((d)[0]), "+f"((d)[1]), "+f"((d)[2]), "+f"((d)[3]) \
        : "r"((a)[0]), "r"((a)[1]), "r"((a)[2]), "r"((a)[3]), "r"(b0), "r"(b1))

// ================= embedding =================
__global__ void embed_kernel(const int* __restrict__ tok,
                             const float* __restrict__ we,
                             const float* __restrict__ pt,
                             float* __restrict__ x,
                             fp16* __restrict__ xh)
{
    int m = blockIdx.x;
    int t = tok[m];
    const float* wr = we + (size_t)t * DD;
    const float* pr = pt + (size_t)t * DD;
    size_t base = (size_t)m * DD;
    for (int j = threadIdx.x; j < DD; j += blockDim.x) {
        float v = wr[j] + pr[j];
        x[base + j] = v;
        xh[base + j] = __float2half_rn(v);
    }
}

// ========== weight transpose + fp16 round ==========
__global__ __launch_bounds__(256)
void wsplit_kernel(const float* __restrict__ W, fp16* __restrict__ Th, int K, int N)
{
    __shared__ float s[32][33];
    int nb = blockIdx.x * 32, kb = blockIdx.y * 32;
    int tx = threadIdx.x & 31, ty = threadIdx.x >> 5;
    #pragma unroll
    for (int j = 0; j < 4; j++)
        s[ty + 8*j][tx] = W[(size_t)(kb + ty + 8*j) * N + nb + tx];
    __syncthreads();
    #pragma unroll
    for (int j = 0; j < 4; j++) {
        float v = s[tx][ty + 8*j];
        Th[(size_t)(nb + ty + 8*j) * K + kb + tx] = __float2half_rn(v);
    }
}

__global__ void bcat_kernel(const float* __restrict__ a, const float* __restrict__ b,
                            const float* __restrict__ c, float* __restrict__ dst, int n)
{
    int i = blockIdx.x * blockDim.x + threadIdx.x;
    if (i < n) { dst[i] = a[i]; dst[n + i] = b[i]; dst[2*n + i] = c[i]; }
}

// ================= fp16 mma.sync GEMM: BM=64, BN=128, BK=64, 3-stage, 3 CTAs/SM =====
// mode 0: fp32+bias; 1: relu->fp16; 3: QKV remap (z picks q-split/k/v);
// mode 4: split-K partial (z = split index): C_ + z*MTOK*N, no bias.
// K = loop length along reduction; ldAB = row stride of A and B (full K).
__global__ __launch_bounds__(256, 3)
void gemm_kernel(const fp16* __restrict__ Ah,
                 const fp16* __restrict__ Bh_,
                 const float* __restrict__ bias_, 
                 float* __restrict__ C_, fp16* __restrict__ Ch, fp16* __restrict__ Cl,
                 fp16* __restrict__ Khp,
                 int K, int ldAB, int N, int mode, size_t zsB, size_t zsBias)
{
    constexpr int BM = 64;
    constexpr int SA = BM * 128;            // 8192
    constexpr int SB = 16384;               // B: 128 rows x 64 fp16
    constexpr int STAGE = SA + SB;          // 24576
    constexpr int NP = 2;

    extern __shared__ char smem[];
    const uint32_t sb = smem_u32(smem);
    const int tid = threadIdx.x;
    const int lane = tid & 31, wid = tid >> 5;
    const int WM = wid & 1;
    const int WN = wid >> 1;
    const int m0 = blockIdx.y * BM, n0 = blockIdx.x * 128;

    const size_t koff = (mode == 4) ? (size_t)blockIdx.z * K : 0;
    const fp16* Bh = Bh_ + blockIdx.z * zsB;
    const float* bias = bias_ + blockIdx.z * zsBias;
    float* C = C_;
    if (mode == 4) C += (size_t)blockIdx.z * ((size_t)MTOK * N);

    const int lrow = tid >> 3, lkg = tid & 7;
    const uint32_t so = (uint32_t)(lrow * 128 + ((lkg ^ (lrow & 7)) << 4));
    const fp16* gAh0 = Ah + (size_t)(m0 + lrow) * ldAB + koff + lkg * 8;
    const fp16* gBh0 = Bh + (size_t)(n0 + lrow) * ldAB + koff + lkg * 8;

    int matA = lane >> 3;
    int arow_local = ((matA & 1) << 3) + (lane & 7);
    int akgbit = matA >> 1;
    uint32_t offA[2][4];
    #pragma unroll
    for (int mt = 0; mt < 2; mt++) {
        int row = WM * 32 + mt * 16 + arow_local;
        #pragma unroll
        for (int ks = 0; ks < 4; ks++)
            offA[mt][ks] = (uint32_t)(row * 128 + (((ks * 2 + akgbit) ^ (row & 7)) << 4));
    }
    int brow_local = ((matA >> 1) << 3) + (lane & 7);
    int bkgbit = matA & 1;
    uint32_t offB[NP][4];
    #pragma unroll
    for (int np = 0; np < NP; np++) {
        int row = WN * (NP * 16) + np * 16 + brow_local;
        #pragma unroll
        for (int ks = 0; ks < 4; ks++)
            offB[np][ks] = (uint32_t)(row * 128 + (((ks * 2 + bkgbit) ^ (row & 7)) << 4));
    }

    float acc[2][2*NP][4];
    #pragma unroll
    for (int i = 0; i < 2; i++)
        #pragma unroll
        for (int j = 0; j < 2*NP; j++)
            #pragma unroll
            for (int qq = 0; qq < 4; qq++) acc[i][j][qq] = 0.f;

    const int NC = K >> 6;

    auto load_stage = [&](int stage, int chunk) {
        uint32_t base = sb + stage * STAGE;
        size_t gk = (size_t)(chunk << 6);
        #pragma unroll
        for (int t = 0; t < 2; t++)
            CP_ASYNC16(base      + so + 4096u*t, gAh0 + (size_t)(32*t) * ldAB + gk);
        #pragma unroll
        for (int t = 0; t < 4; t++)
            CP_ASYNC16(base + SA + so + 4096u*t, gBh0 + (size_t)(32*t) * ldAB + gk);
    };

    load_stage(0, 0); CP_COMMIT();
    if (NC > 1) load_stage(1, 1);
    CP_COMMIT();

    int cur = 0;
    for (int i = 0; i < NC; i++) {
        CP_WAIT1();
        __syncthreads();

        uint32_t base = sb + cur * STAGE;
        uint32_t sAh = base, sBh = base + SA;

        #pragma unroll
        for (int ks = 0; ks < 4; ks++) {
            uint32_t ah[2][4];
            #pragma unroll
            for (int mt = 0; mt < 2; mt++)
                LDSM_X4(ah[mt][0], ah[mt][1], ah[mt][2], ah[mt][3], sAh + offA[mt][ks]);
            #pragma unroll
            for (int np = 0; np < NP; np++) {
                uint32_t bh[4];
                LDSM_X4(bh[0], bh[1], bh[2], bh[3], sBh + offB[np][ks]);
                #pragma unroll
                for (int mt = 0; mt < 2; mt++) {
                    MMA_F16(acc[mt][np*2+0], ah[mt], bh[0], bh[1]);
                    MMA_F16(acc[mt][np*2+1], ah[mt], bh[2], bh[3]);
                }
            }
        }
        __syncthreads();
        if (i + 2 < NC) {
            int pf = cur + 2; if (pf >= 3) pf -= 3;
            load_stage(pf, i + 2);
        }
        CP_COMMIT();
        cur = (cur + 1 == 3) ? 0 : cur + 1;
    }

    // -------- epilogue --------
    #pragma unroll
    for (int mt = 0; mt < 2; mt++) {
        int r0 = m0 + WM * 32 + mt * 16 + (lane >> 2);
        int r1 = r0 + 8;
        #pragma unroll
        for (int nt = 0; nt < 2*NP; nt++) {
            int c = n0 + WN * (NP * 16) + nt * 8 + ((lane & 3) << 1);
            float v00 = acc[mt][nt][0], v01 = acc[mt][nt][1];
            float v10 = acc[mt][nt][2], v11 = acc[mt][nt][3];
            if (mode == 4) {
                *(float2*)(C + (size_t)r0 * N + c) = make_float2(v00, v01);
                *(float2*)(C + (size_t)r1 * N + c) = make_float2(v10, v11);
                continue;
            }
            float2 bv = *(const float2*)(bias + c);
            v00 += bv.x; v01 += bv.y; v10 += bv.x; v11 += bv.y;
            if (mode == 0) {
                *(float2*)(C + (size_t)r0 * N + c) = make_float2(v00, v01);
                *(float2*)(C + (size_t)r1 * N + c) = make_float2(v10, v11);
            } else if (mode == 1) {
                v00 = fmaxf(v00, 0.f); v01 = fmaxf(v01, 0.f);
                v10 = fmaxf(v10, 0.f); v11 = fmaxf(v11, 0.f);
                *(__half2*)(Ch + (size_t)r0 * N + c) =
                    __halves2half2(__float2half_rn(v00), __float2half_rn(v01));
                *(__half2*)(Ch + (size_t)r1 * N + c) =
                    __halves2half2(__float2half_rn(v10), __float2half_rn(v11));
            } else {
                // mode 3: QKV remap
                int b0_ = r0 >> 9, s0_ = r0 & 511;
                int b1_ = r1 >> 9, s1_ = r1 & 511;
                int h_ = c >> 6, d_ = c & 63;
                size_t i0 = ((((size_t)b0_ * HH + h_) * SS + s0_) << 6) + d_;
                size_t i1 = ((((size_t)b1_ * HH + h_) * SS + s1_) << 6) + d_;
                int z = blockIdx.z;
                if (z == 0) {
                    fp16 h0,l0,h1,l1,h2,l2,h3,l3;
                    split_fp16(v00,h0,l0); split_fp16(v01,h1,l1);
                    split_fp16(v10,h2,l2); split_fp16(v11,h3,l3);
                    *(__half2*)(Ch + i0) = __halves2half2(h0, h1);
                    *(__half2*)(Cl + i0) = __halves2half2(l0, l1);
                    *(__half2*)(Ch + i1) = __halves2half2(h2, h3);
                    *(__half2*)(Cl + i1) = __halves2half2(l2, l3);
                } else if (z == 1) {
                    *(__half2*)(Khp + i0) = __halves2half2(__float2half_rn(v00), __float2half_rn(v01));
                    *(__half2*)(Khp + i1) = __halves2half2(__float2half_rn(v10), __float2half_rn(v11));
                } else {
                    *(float2*)(C + i0) = make_float2(v00, v01);
                    *(float2*)(C + i1) = make_float2(v10, v11);
                }
            }
        }
    }
}

// ================= fused attention: tensor-core scores + fp32 softmax/AV =================
#define SC_B   0
#define RA_B   (32*513*4)              // 65664
#define RB_B   (RA_B + 24576)          // 90240
#define ATT_SMEM (RB_B + 17408)        // 107648

__global__ __launch_bounds__(256, 2)
void attn_kernel(const fp16* __restrict__ qh, const fp16* __restrict__ ql,
                 const fp16* __restrict__ kh, const float* __restrict__ v,
                 const int* __restrict__ tok,
                 float* __restrict__ probs, fp16* __restrict__ avh)
{
    extern __shared__ char smc[];
    float* sm = (float*)smc;
    float* sc = sm;                        // 32 x 513
    const uint32_t sb = smem_u32(smc);
    int qb = blockIdx.x, h = blockIdx.y, b = blockIdx.z;
    int tid = threadIdx.x;
    int w = tid >> 5, lane = tid & 31;

    const size_t bh_off = (((size_t)b * HH + h) * SS) << 6;
    const fp16* qh_g = qh + bh_off + ((size_t)qb * 32 << 6);
    const fp16* ql_g = ql + bh_off + ((size_t)qb * 32 << 6);
    const fp16* kh_g = kh + bh_off;
    const float* v_g = v + bh_off;
    const int* tb = tok + b * SS;

    auto pf_k = [&](int ch, int buf) {
        uint32_t sdst = sb + RA_B + 8192 + buf * 8192;
        const fp16* src = kh_g + (size_t)(ch * 64) * 64;
        #pragma unroll
        for (int t = 0; t < 2; t++) {
            int j = tid + 256 * t;
            int row = j >> 3, kg = j & 7;
            CP_ASYNC16(sdst + (uint32_t)(row * 128 + ((kg ^ (row & 7)) << 4)),
                       src + (size_t)row * 64 + kg * 8);
        }
    };
    {
        int row = tid >> 3, kg = tid & 7;
        uint32_t so = (uint32_t)(row * 128 + ((kg ^ (row & 7)) << 4));
        CP_ASYNC16(sb + RA_B + so,        qh_g + (size_t)row * 64 + kg * 8);
        CP_ASYNC16(sb + RA_B + 4096 + so, ql_g + (size_t)row * 64 + kg * 8);
    }
    pf_k(0, 0);
    CP_COMMIT();

    int qh16 = (w >> 2) * 16;
    int keyq = w & 3;
    int matA = lane >> 3;
    int arow = qh16 + ((matA & 1) << 3) + (lane & 7);
    int akg = matA >> 1;
    uint32_t offQ[4];
    #pragma unroll
    for (int ks = 0; ks < 4; ks++)
        offQ[ks] = (uint32_t)(arow * 128 + (((ks * 2 + akg) ^ (arow & 7)) << 4));
    int brow = keyq * 16 + ((matA >> 1) << 3) + (lane & 7);
    int bkg = matA & 1;
    uint32_t offK[4];
    #pragma unroll
    for (int ks = 0; ks < 4; ks++)
        offK[ks] = (uint32_t)(brow * 128 + (((ks * 2 + bkg) ^ (brow & 7)) << 4));

    const uint32_t qhb = sb + RA_B, qlb = sb + RA_B + 4096;

    for (int ch = 0; ch < 8; ch++) {
        if (ch < 7) pf_k(ch + 1, (ch + 1) & 1);
        CP_COMMIT();
        CP_WAIT1();
        __syncthreads();
        uint32_t kb = sb + RA_B + 8192 + (ch & 1) * 8192;

        float c0[4] = {0.f,0.f,0.f,0.f}, c1[4] = {0.f,0.f,0.f,0.f};
        #pragma unroll
        for (int ks = 0; ks < 4; ks++) {
            uint32_t ah[4], al[4], bbv[4];
            LDSM_X4(ah[0], ah[1], ah[2], ah[3], qhb + offQ[ks]);
            LDSM_X4(al[0], al[1], al[2], al[3], qlb + offQ[ks]);
            LDSM_X4(bbv[0], bbv[1], bbv[2], bbv[3], kb + offK[ks]);
            MMA_F16(c0, ah, bbv[0], bbv[1]);
            MMA_F16(c0, al, bbv[0], bbv[1]);
            MMA_F16(c1, ah, bbv[2], bbv[3]);
            MMA_F16(c1, al, bbv[2], bbv[3]);
        }
        int tc = lane >> 2, tcol = (lane & 3) * 2;
        int q0 = qh16 + tc, q1 = q0 + 8;
        #pragma unroll
        for (int nt = 0; nt < 2; nt++) {
            float* cc = nt ? c1 : c0;
            int key0 = ch * 64 + keyq * 16 + nt * 8 + tcol;
            bool m0 = (tb[key0] == 0), m1 = (tb[key0 + 1] == 0);
            sc[q0 * 513 + key0]     = m0 ? -INFINITY : cc[0] * 0.125f;
            sc[q0 * 513 + key0 + 1] = m1 ? -INFINITY : cc[1] * 0.125f;
            sc[q1 * 513 + key0]     = m0 ? -INFINITY : cc[2] * 0.125f;
            sc[q1 * 513 + key0 + 1] = m1 ? -INFINITY : cc[3] * 0.125f;
        }
        __syncthreads();
    }

    auto pf_v = [&](const float* gsrc, int buf) {
        uint32_t sdst = sb + (buf ? RB_B : RA_B);
        #pragma unroll
        for (int t = 0; t < 4; t++) {
            int j = tid + 256 * t;
            int row = j >> 4, c4 = j & 15;
            CP_ASYNC16(sdst + (uint32_t)(row * 68 + c4 * 4) * 4,
                       gsrc + (size_t)row * 64 + c4 * 4);
        }
    };
    pf_v(v_g, 0); CP_COMMIT();

    #pragma unroll 1
    for (int rr = 0; rr < 4; rr++) {
        int row = w * 4 + rr;
        float* srow = sc + row * 513;
        float m = -INFINITY;
        for (int j = lane; j < 512; j += 32) m = fmaxf(m, srow[j]);
        #pragma unroll
        for (int o = 16; o > 0; o >>= 1) m = fmaxf(m, __shfl_xor_sync(~0u, m, o));
        float sum = 0.f;
        for (int j = lane; j < 512; j += 32) {
            float e = __expf(srow[j] - m);
            srow[j] = e; sum += e;
        }
        #pragma unroll
        for (int o = 16; o > 0; o >>= 1) sum += __shfl_xor_sync(~0u, sum, o);
        float inv = 1.f / sum;
        float* prow = probs + ((((size_t)b * HH + h) * SS + qb * 32 + row) << 9);
        for (int j = lane; j < 512; j += 32) {
            float p = srow[j] * inv;
            srow[j] = p;
            prow[j] = p;
        }
    }
    __syncthreads();

    int ql_ = tid & 31, dg = tid >> 5;
    float a8[8] = {};
    for (int ch = 0; ch < 8; ch++) {
        if (ch < 7) pf_v(v_g + (size_t)(ch + 1) * 64 * 64, (ch + 1) & 1);
        CP_COMMIT();
        CP_WAIT1();
        __syncthreads();
        const float* kvb = sm + ((ch & 1) ? (RB_B >> 2) : (RA_B >> 2));
        const float* srow = sc + ql_ * 513 + ch * 64;
        #pragma unroll 4
        for (int kk = 0; kk < 64; kk++) {
            float s = srow[kk];
            float4 v0 = *(const float4*)(kvb + kk * 68 + dg * 8);
            float4 v1 = *(const float4*)(kvb + kk * 68 + dg * 8 + 4);
            a8[0] = fmaf(s, v0.x, a8[0]); a8[1] = fmaf(s, v0.y, a8[1]);
            a8[2] = fmaf(s, v0.z, a8[2]); a8[3] = fmaf(s, v0.w, a8[3]);
            a8[4] = fmaf(s, v1.x, a8[4]); a8[5] = fmaf(s, v1.y, a8[5]);
            a8[6] = fmaf(s, v1.z, a8[6]); a8[7] = fmaf(s, v1.w, a8[7]);
        }
        __syncthreads();
    }
    size_t o = ((size_t)(b * SS + qb * 32 + ql_) << 10) + h * 64 + dg * 8;
    uint32_t ph[4];
    #pragma unroll
    for (int i = 0; i < 4; i++) {
        ph[i] = ((uint32_t)__half_as_ushort(__float2half_rn(a8[2*i+1])) << 16)
              | __half_as_ushort(__float2half_rn(a8[2*i]));
    }
    *(uint4*)(avh + o) = make_uint4(ph[0], ph[1], ph[2], ph[3]);
}

// ======== layernorm of (p0 + p1 + res + bias), fp16 out ========
__global__ __launch_bounds__(256)
void ln_sum_kernel(const float* __restrict__ p0, const float* __restrict__ p1,
                   const float* __restrict__ res, const float* __restrict__ bias,
                   float* __restrict__ out, fp16* __restrict__ oh)
{
    int row = blockIdx.x;
    int tid = threadIdx.x;
    size_t base = (size_t)row * DD;
    float v0 = p0[base + tid]       + p1[base + tid]       + res[base + tid]       + bias[tid];
    float v1 = p0[base + tid + 256] + p1[base + tid + 256] + res[base + tid + 256] + bias[tid + 256];
    float v2 = p0[base + tid + 512] + p1[base + tid + 512] + res[base + tid + 512] + bias[tid + 512];
    float v3 = p0[base + tid + 768] + p1[base + tid + 768] + res[base + tid + 768] + bias[tid + 768];
    float s = v0 + v1 + v2 + v3;

    __shared__ float sh[32];
    #pragma unroll
    for (int o = 16; o > 0; o >>= 1) s += __shfl_down_sync(~0u, s, o);
    if ((tid & 31) == 0) sh[tid >> 5] = s;
    __syncthreads();
    if (tid < 8) {
        s = sh[tid];
        #pragma unroll
        for (int o = 4; o > 0; o >>= 1) s += __shfl_down_sync(0xffu, s, o);
        if (tid == 0) sh[0] = s;
    }
    __syncthreads();
    float mean = sh[0] * (1.f / 1024.f);
    float d0 = v0 - mean, d1 = v1 - mean, d2 = v2 - mean, d3 = v3 - mean;
    float qv = d0*d0 + d1*d1 + d2*d2 + d3*d3;
    __syncthreads();
    #pragma unroll
    for (int o = 16; o > 0; o >>= 1) qv += __shfl_down_sync(~0u, qv, o);
    if ((tid & 31) == 0) sh[tid >> 5] = qv;
    __syncthreads();
    if (tid < 8) {
        qv = sh[tid];
        #pragma unroll
        for (int o = 4; o > 0; o >>= 1) qv += __shfl_down_sync(0xffu, qv, o);
        if (tid == 0) sh[0] = qv;
    }
    __syncthreads();
    float inv = rsqrtf(sh[0] * (1.f / 1024.f) + 1e-5f);
    #pragma unroll
    for (int jj = 0; jj < 4; jj++) {
        float d = (jj == 0 ? d0 : jj == 1 ? d1 : jj == 2 ? d2 : d3);
        float val = d * inv;
        int idx = tid + jj * 256;
        out[base + idx] = val;
        oh[base + idx] = __float2half_rn(val);
    }
}

// ================= host driver =================
extern "C" void kernel_launch(void* const* d_in, const int* in_sizes, int n_in,
                              void* d_out, int out_size)
{
    const int*   tok = (const int*)d_in[0];
    const float* we  = (const float*)d_in[1];
    const float* pt  = (const float*)d_in[2];
    const float* Wq  = (const float*)d_in[3];  const float* bq = (const float*)d_in[4];
    const float* Wk  = (const float*)d_in[5];  const float* bk = (const float*)d_in[6];
    const float* Wv  = (const float*)d_in[7];  const float* bv = (const float*)d_in[8];
    const float* Wo  = (const float*)d_in[9];  const float* bo = (const float*)d_in[10];
    const float* W1  = (const float*)d_in[11]; const float* b1 = (const float*)d_in[12];
    const float* W2  = (const float*)d_in[13]; const float* b2 = (const float*)d_in[14];
    float* out = (float*)d_out;

    float *x, *x1p, *bqkv, *vf, *part;
    fp16 *xh, *qhp, *qlp, *khp, *avh, *x1h, *ffh;
    cudaGetSymbolAddress((void**)&x,   g_x);
    cudaGetSymbolAddress((void**)&xh,  g_xh);
    cudaGetSymbolAddress((void**)&qhp, g_qh);  cudaGetSymbolAddress((void**)&qlp, g_ql);
    cudaGetSymbolAddress((void**)&khp, g_kh);  cudaGetSymbolAddress((void**)&vf,  g_v);
    cudaGetSymbolAddress((void**)&avh, g_avh);
    cudaGetSymbolAddress((void**)&x1p, g_x1);
    cudaGetSymbolAddress((void**)&x1h, g_x1h);
    cudaGetSymbolAddress((void**)&ffh, g_ffh);
    cudaGetSymbolAddress((void**)&part, g_part);
    cudaGetSymbolAddress((void**)&bqkv, g_bqkv);

    fp16 *wqkvT, *woT, *w1T, *w2T;
    cudaGetSymbolAddress((void**)&wqkvT, g_wqkvT);
    cudaGetSymbolAddress((void**)&woT, g_woT);
    cudaGetSymbolAddress((void**)&w1T, g_w1T);
    cudaGetSymbolAddress((void**)&w2T, g_w2T);

    const int GSMEM = 3 * (64 * 128 + 128 * 128);   // 73728
    cudaFuncSetAttribute(gemm_kernel, cudaFuncAttributeMaxDynamicSharedMemorySize, GSMEM);
    cudaFuncSetAttribute(attn_kernel, cudaFuncAttributeMaxDynamicSharedMemorySize, ATT_SMEM);

    static cudaStream_t s2 = nullptr;
    static cudaEvent_t eFork = nullptr, eLay[LL];
    if (!s2) {
        cudaStreamCreate(&s2);
        cudaEventCreateWithFlags(&eFork, cudaEventDisableTiming);
        for (int l = 0; l < LL; l++) cudaEventCreateWithFlags(&eLay[l], cudaEventDisableTiming);
    }

    const size_t PROJ = (size_t)DD * DD;
    const size_t WQKV = (size_t)LL * DD * DD;
    const size_t W1SZ = (size_t)DD * DFF;
    const size_t W2SZ = (size_t)DFF * DD;
    const size_t CORR = (size_t)BB * HH * SS * SS;
    const size_t PSZ  = (size_t)MTOK * DD;

    auto split_layer = [&](int l, cudaStream_t st) {
        dim3 gP(DD/32, DD/32);
        wsplit_kernel<<<gP, 256, 0, st>>>(Wq + l*PROJ, wqkvT + l*PROJ,          DD, DD);
        wsplit_kernel<<<gP, 256, 0, st>>>(Wk + l*PROJ, wqkvT + WQKV + l*PROJ,   DD, DD);
        wsplit_kernel<<<gP, 256, 0, st>>>(Wv + l*PROJ, wqkvT + 2*WQKV + l*PROJ, DD, DD);
        wsplit_kernel<<<gP, 256, 0, st>>>(Wo + l*PROJ, woT + l*PROJ, DD, DD);
        dim3 g1(DFF/32, DD/32);
        wsplit_kernel<<<g1, 256, 0, st>>>(W1 + l*W1SZ, w1T + l*W1SZ, DD, DFF);
        dim3 g2(DD/32, DFF/32);
        wsplit_kernel<<<g2, 256, 0, st>>>(W2 + l*W2SZ, w2T + l*W2SZ, DFF, DD);
    };

    bcat_kernel<<<(LL*DD + 255)/256, 256>>>(bq, bk, bv, bqkv, LL*DD);
    split_layer(0, (cudaStream_t)0);
    embed_kernel<<<MTOK, 256>>>(tok, we, pt, x, xh);

    cudaEventRecord(eFork, (cudaStream_t)0);
    cudaStreamWaitEvent(s2, eFork, 0);
    for (int l = 1; l < LL; l++) {
        split_layer(l, s2);
        cudaEventRecord(eLay[l], s2);
    }

    dim3 gQKV(DD / 128, MTOK / 64, 3);    // 768 CTAs
    dim3 gFF (DFF / 128, MTOK / 64);      // 1024 CTAs
    dim3 gSK (DD / 128, MTOK / 64, 2);    // 512 CTAs (split-K2)
    dim3 gA  (SS / 32, HH, BB);           // (16,16,4)

    for (int l = 0; l < LL; l++) {
        if (l > 0) cudaStreamWaitEvent((cudaStream_t)0, eLay[l], 0);

        gemm_kernel<<<gQKV, 256, GSMEM>>>(xh, wqkvT + l*PROJ,
                                          bqkv + l*DD, vf, qhp, qlp, khp,
                                          DD, DD, DD, 3, WQKV, (size_t)LL*DD);

        float* probs_l = out + (size_t)MTOK * DD + (size_t)l * CORR;
        attn_kernel<<<gA, 256, ATT_SMEM>>>(qhp, qlp, khp, vf, tok, probs_l, avh);

        // O-proj: split-K2 partials, then fused sum+res+bias+LN
        gemm_kernel<<<gSK, 256, GSMEM>>>(avh, woT + l*PROJ, bo + l*DD,
                                         part, nullptr, nullptr, nullptr,
                                         DD/2, DD, DD, 4, 0, 0);
        ln_sum_kernel<<<MTOK, 256>>>(part, part + PSZ, x, bo + l*DD, x1p, x1h);

        gemm_kernel<<<gFF, 256, GSMEM>>>(x1h, w1T + l*W1SZ, b1 + l*DFF,
                                         nullptr, ffh, nullptr, nullptr,
                                         DD, DD, DFF, 1, 0, 0);

        // FFN2: split-K2 partials, then fused sum+res+bias+LN
        gemm_kernel<<<gSK, 256, GSMEM>>>(ffh, w2T + l*W2SZ, b2 + l*DD,
                                         part, nullptr, nullptr, nullptr,
                                         DFF/2, DFF, DD, 4, 0, 0);
        float* xdst = (l == LL - 1) ? out : x;
        ln_sum_kernel<<<MTOK, 256>>>(part, part + PSZ, x1p, b2 + l*DD, xdst, xh);
    }
}

// round 17
// speedup vs baseline: 1.3225x; 1.2351x over previous
#include <cuda_runtime.h>
#include <cuda_fp16.h>
#include <math.h>
#include <stdint.h>

// Problem constants
#define BB 4
#define SS 512
#define DD 1024
#define HH 16
#define DHH 64
#define DFF 4096
#define LL 6
#define MTOK (BB*SS)          // 2048 token rows

typedef __half fp16;

// ================= device scratch =================
__device__ float g_x  [MTOK*DD];
__device__ fp16  g_xh [MTOK*DD];
__device__ fp16  g_qh [MTOK*DD],  g_ql [MTOK*DD];   // Q fp16 split [B,H,S,64]
__device__ fp16  g_kh [MTOK*DD];                    // K fp16 [B,H,S,64]
__device__ fp16  g_vh [MTOK*DD];                    // V fp16 [B,H,S,64]
__device__ fp16  g_avh[MTOK*DD];
__device__ float g_x1 [MTOK*DD];
__device__ fp16  g_x1h[MTOK*DD];
__device__ fp16  g_ffh[MTOK*DFF];
__device__ float g_part[2*MTOK*DD];                 // split-K partials

__device__ fp16 g_wqkvT[3*LL*DD*DD];   // [3][L][N][K]
__device__ fp16 g_woT[LL*DD*DD];
__device__ fp16 g_w1T[LL*DD*DFF];
__device__ fp16 g_w2T[LL*DFF*DD];
__device__ float g_bqkv[3*LL*DD];

// ================= helpers =================
__device__ __forceinline__ uint32_t smem_u32(const void* p) {
    uint32_t a;
    asm("{ .reg .u64 t; cvta.to.shared.u64 t, %1; cvt.u32.u64 %0, t; }" : "=r"(a) : "l"(p));
    return a;
}
__device__ __forceinline__ void split_fp16(float v, fp16& h, fp16& l) {
    h = __float2half_rn(v);
    l = __float2half_rn(v - __half2float(h));
}

#define CP_ASYNC16(sa, ga) \
    asm volatile("cp.async.cg.shared.global [%0], [%1], 16;" :: "r"(sa), "l"(ga) : "memory")
#define CP_COMMIT() asm volatile("cp.async.commit_group;" ::: "memory")
#define CP_WAIT1()  asm volatile("cp.async.wait_group 1;" ::: "memory")
#define CP_WAIT0()  asm volatile("cp.async.wait_group 0;" ::: "memory")

#define LDSM_X4(r0,r1,r2,r3, addr) \
    asm volatile("ldmatrix.sync.aligned.m8n8.x4.shared.b16 {%0,%1,%2,%3}, [%4];" \
        : "=r"(r0), "=r"(r1), "=r"(r2), "=r"(r3) : "r"(addr))

#define LDSM_X4_T(r0,r1,r2,r3, addr) \
    asm volatile("ldmatrix.sync.aligned.m8n8.x4.trans.shared.b16 {%0,%1,%2,%3}, [%4];" \
        : "=r"(r0), "=r"(r1), "=r"(r2), "=r"(r3) : "r"(addr))

#define MMA_F16(d, a, b0, b1) \
    asm volatile("mma.sync.aligned.m16n8k16.row.col.f32.f16.f16.f32 " \
        "{%0,%1,%2,%3}, {%4,%5,%6,%7}, {%8,%9}, {%0,%1,%2,%3};" \
        : "+f"((d)[0]), "+f"((d)[1]), "+f"((d)[2]), "+f"((d)[3]) \
        : "r"((a)[0]), "r"((a)[1]), "r"((a)[2]), "r"((a)[3]), "r"(b0), "r"(b1))

// ================= embedding =================
__global__ void embed_kernel(const int* __restrict__ tok,
                             const float* __restrict__ we,
                             const float* __restrict__ pt,
                             float* __restrict__ x,
                             fp16* __restrict__ xh)
{
    int m = blockIdx.x;
    int t = tok[m];
    const float* wr = we + (size_t)t * DD;
    const float* pr = pt + (size_t)t * DD;
    size_t base = (size_t)m * DD;
    for (int j = threadIdx.x; j < DD; j += blockDim.x) {
        float v = wr[j] + pr[j];
        x[base + j] = v;
        xh[base + j] = __float2half_rn(v);
    }
}

// ========== weight transpose + fp16 round ==========
__global__ __launch_bounds__(256)
void wsplit_kernel(const float* __restrict__ W, fp16* __restrict__ Th, int K, int N)
{
    __shared__ float s[32][33];
    int nb = blockIdx.x * 32, kb = blockIdx.y * 32;
    int tx = threadIdx.x & 31, ty = threadIdx.x >> 5;
    #pragma unroll
    for (int j = 0; j < 4; j++)
        s[ty + 8*j][tx] = W[(size_t)(kb + ty + 8*j) * N + nb + tx];
    __syncthreads();
    #pragma unroll
    for (int j = 0; j < 4; j++) {
        float v = s[tx][ty + 8*j];
        Th[(size_t)(nb + ty + 8*j) * K + kb + tx] = __float2half_rn(v);
    }
}

__global__ void bcat_kernel(const float* __restrict__ a, const float* __restrict__ b,
                            const float* __restrict__ c, float* __restrict__ dst, int n)
{
    int i = blockIdx.x * blockDim.x + threadIdx.x;
    if (i < n) { dst[i] = a[i]; dst[n + i] = b[i]; dst[2*n + i] = c[i]; }
}

// ================= fp16 mma.sync GEMM: BM=64, BN=128, BK=64, 3-stage, 3 CTAs/SM =====
// mode 0: fp32+bias; 1: relu->fp16; 3: QKV remap (z=0 Q split, z=1 K fp16, z=2 V fp16);
// mode 4: split-K partial (z = split index): C_ + z*MTOK*N, no bias.
__global__ __launch_bounds__(256, 3)
void gemm_kernel(const fp16* __restrict__ Ah,
                 const fp16* __restrict__ Bh_,
                 const float* __restrict__ bias_,
                 float* __restrict__ C_, fp16* __restrict__ Ch, fp16* __restrict__ Cl,
                 fp16* __restrict__ Khp, fp16* __restrict__ Vhp,
                 int K, int ldAB, int N, int mode, size_t zsB, size_t zsBias)
{
    constexpr int BM = 64;
    constexpr int SA = BM * 128;            // 8192
    constexpr int SB = 16384;               // B: 128 rows x 64 fp16
    constexpr int STAGE = SA + SB;          // 24576
    constexpr int NP = 2;

    extern __shared__ char smem[];
    const uint32_t sb = smem_u32(smem);
    const int tid = threadIdx.x;
    const int lane = tid & 31, wid = tid >> 5;
    const int WM = wid & 1;
    const int WN = wid >> 1;
    const int m0 = blockIdx.y * BM, n0 = blockIdx.x * 128;

    const size_t koff = (mode == 4) ? (size_t)blockIdx.z * K : 0;
    const fp16* Bh = Bh_ + blockIdx.z * zsB;
    const float* bias = bias_ + blockIdx.z * zsBias;
    float* C = C_;
    if (mode == 4) C += (size_t)blockIdx.z * ((size_t)MTOK * N);

    const int lrow = tid >> 3, lkg = tid & 7;
    const uint32_t so = (uint32_t)(lrow * 128 + ((lkg ^ (lrow & 7)) << 4));
    const fp16* gAh0 = Ah + (size_t)(m0 + lrow) * ldAB + koff + lkg * 8;
    const fp16* gBh0 = Bh + (size_t)(n0 + lrow) * ldAB + koff + lkg * 8;

    int matA = lane >> 3;
    int arow_local = ((matA & 1) << 3) + (lane & 7);
    int akgbit = matA >> 1;
    uint32_t offA[2][4];
    #pragma unroll
    for (int mt = 0; mt < 2; mt++) {
        int row = WM * 32 + mt * 16 + arow_local;
        #pragma unroll
        for (int ks = 0; ks < 4; ks++)
            offA[mt][ks] = (uint32_t)(row * 128 + (((ks * 2 + akgbit) ^ (row & 7)) << 4));
    }
    int brow_local = ((matA >> 1) << 3) + (lane & 7);
    int bkgbit = matA & 1;
    uint32_t offB[NP][4];
    #pragma unroll
    for (int np = 0; np < NP; np++) {
        int row = WN * (NP * 16) + np * 16 + brow_local;
        #pragma unroll
        for (int ks = 0; ks < 4; ks++)
            offB[np][ks] = (uint32_t)(row * 128 + (((ks * 2 + bkgbit) ^ (row & 7)) << 4));
    }

    float acc[2][2*NP][4];
    #pragma unroll
    for (int i = 0; i < 2; i++)
        #pragma unroll
        for (int j = 0; j < 2*NP; j++)
            #pragma unroll
            for (int qq = 0; qq < 4; qq++) acc[i][j][qq] = 0.f;

    const int NC = K >> 6;

    auto load_stage = [&](int stage, int chunk) {
        uint32_t base = sb + stage * STAGE;
        size_t gk = (size_t)(chunk << 6);
        #pragma unroll
        for (int t = 0; t < 2; t++)
            CP_ASYNC16(base      + so + 4096u*t, gAh0 + (size_t)(32*t) * ldAB + gk);
        #pragma unroll
        for (int t = 0; t < 4; t++)
            CP_ASYNC16(base + SA + so + 4096u*t, gBh0 + (size_t)(32*t) * ldAB + gk);
    };

    load_stage(0, 0); CP_COMMIT();
    if (NC > 1) load_stage(1, 1);
    CP_COMMIT();

    int cur = 0;
    for (int i = 0; i < NC; i++) {
        CP_WAIT1();
        __syncthreads();

        uint32_t base = sb + cur * STAGE;
        uint32_t sAh = base, sBh = base + SA;

        #pragma unroll
        for (int ks = 0; ks < 4; ks++) {
            uint32_t ah[2][4];
            #pragma unroll
            for (int mt = 0; mt < 2; mt++)
                LDSM_X4(ah[mt][0], ah[mt][1], ah[mt][2], ah[mt][3], sAh + offA[mt][ks]);
            #pragma unroll
            for (int np = 0; np < NP; np++) {
                uint32_t bh[4];
                LDSM_X4(bh[0], bh[1], bh[2], bh[3], sBh + offB[np][ks]);
                #pragma unroll
                for (int mt = 0; mt < 2; mt++) {
                    MMA_F16(acc[mt][np*2+0], ah[mt], bh[0], bh[1]);
                    MMA_F16(acc[mt][np*2+1], ah[mt], bh[2], bh[3]);
                }
            }
        }
        __syncthreads();
        if (i + 2 < NC) {
            int pf = cur + 2; if (pf >= 3) pf -= 3;
            load_stage(pf, i + 2);
        }
        CP_COMMIT();
        cur = (cur + 1 == 3) ? 0 : cur + 1;
    }

    // -------- epilogue --------
    #pragma unroll
    for (int mt = 0; mt < 2; mt++) {
        int r0 = m0 + WM * 32 + mt * 16 + (lane >> 2);
        int r1 = r0 + 8;
        #pragma unroll
        for (int nt = 0; nt < 2*NP; nt++) {
            int c = n0 + WN * (NP * 16) + nt * 8 + ((lane & 3) << 1);
            float v00 = acc[mt][nt][0], v01 = acc[mt][nt][1];
            float v10 = acc[mt][nt][2], v11 = acc[mt][nt][3];
            if (mode == 4) {
                *(float2*)(C + (size_t)r0 * N + c) = make_float2(v00, v01);
                *(float2*)(C + (size_t)r1 * N + c) = make_float2(v10, v11);
                continue;
            }
            float2 bv = *(const float2*)(bias + c);
            v00 += bv.x; v01 += bv.y; v10 += bv.x; v11 += bv.y;
            if (mode == 0) {
                *(float2*)(C + (size_t)r0 * N + c) = make_float2(v00, v01);
                *(float2*)(C + (size_t)r1 * N + c) = make_float2(v10, v11);
            } else if (mode == 1) {
                v00 = fmaxf(v00, 0.f); v01 = fmaxf(v01, 0.f);
                v10 = fmaxf(v10, 0.f); v11 = fmaxf(v11, 0.f);
                *(__half2*)(Ch + (size_t)r0 * N + c) =
                    __halves2half2(__float2half_rn(v00), __float2half_rn(v01));
                *(__half2*)(Ch + (size_t)r1 * N + c) =
                    __halves2half2(__float2half_rn(v10), __float2half_rn(v11));
            } else {
                // mode 3: QKV remap
                int b0_ = r0 >> 9, s0_ = r0 & 511;
                int b1_ = r1 >> 9, s1_ = r1 & 511;
                int h_ = c >> 6, d_ = c & 63;
                size_t i0 = ((((size_t)b0_ * HH + h_) * SS + s0_) << 6) + d_;
                size_t i1 = ((((size_t)b1_ * HH + h_) * SS + s1_) << 6) + d_;
                int z = blockIdx.z;
                if (z == 0) {
                    fp16 h0,l0,h1,l1,h2,l2,h3,l3;
                    split_fp16(v00,h0,l0); split_fp16(v01,h1,l1);
                    split_fp16(v10,h2,l2); split_fp16(v11,h3,l3);
                    *(__half2*)(Ch + i0) = __halves2half2(h0, h1);
                    *(__half2*)(Cl + i0) = __halves2half2(l0, l1);
                    *(__half2*)(Ch + i1) = __halves2half2(h2, h3);
                    *(__half2*)(Cl + i1) = __halves2half2(l2, l3);
                } else if (z == 1) {
                    *(__half2*)(Khp + i0) = __halves2half2(__float2half_rn(v00), __float2half_rn(v01));
                    *(__half2*)(Khp + i1) = __halves2half2(__float2half_rn(v10), __float2half_rn(v11));
                } else {
                    *(__half2*)(Vhp + i0) = __halves2half2(__float2half_rn(v00), __float2half_rn(v01));
                    *(__half2*)(Vhp + i1) = __halves2half2(__float2half_rn(v10), __float2half_rn(v11));
                }
            }
        }
    }
}

// ================= fused attention: tensor-core scores + fp32 softmax + tensor-core AV =====
// smem: sc fp32[32][513] | Pb fp16[8 chunks][32][64] (aliases Q/K region) | V fp16 dbl buf
#define SC_B   0
#define PB_B   (32*513*4)              // 65664; P region 32768 B (Q/K alias first 24576 B)
#define VB_B   (PB_B + 32768)          // 98432
#define ATT_SMEM (VB_B + 2*8192)       // 114816

__global__ __launch_bounds__(256, 2)
void attn_kernel(const fp16* __restrict__ qh, const fp16* __restrict__ ql,
                 const fp16* __restrict__ kh, const fp16* __restrict__ vh,
                 const int* __restrict__ tok,
                 float* __restrict__ probs, fp16* __restrict__ avh)
{
    extern __shared__ char smc[];
    float* sm = (float*)smc;
    float* sc = sm;                        // 32 x 513
    const uint32_t sb = smem_u32(smc);
    int qb = blockIdx.x, h = blockIdx.y, b = blockIdx.z;
    int tid = threadIdx.x;
    int w = tid >> 5, lane = tid & 31;

    const size_t bh_off = (((size_t)b * HH + h) * SS) << 6;
    const fp16* qh_g = qh + bh_off + ((size_t)qb * 32 << 6);
    const fp16* ql_g = ql + bh_off + ((size_t)qb * 32 << 6);
    const fp16* kh_g = kh + bh_off;
    const fp16* vh_g = vh + bh_off;
    const int* tb = tok + b * SS;

    auto pf_k = [&](int ch, int buf) {
        uint32_t sdst = sb + PB_B + 8192 + buf * 8192;
        const fp16* src = kh_g + (size_t)(ch * 64) * 64;
        #pragma unroll
        for (int t = 0; t < 2; t++) {
            int j = tid + 256 * t;
            int row = j >> 3, kg = j & 7;
            CP_ASYNC16(sdst + (uint32_t)(row * 128 + ((kg ^ (row & 7)) << 4)),
                       src + (size_t)row * 64 + kg * 8);
        }
    };
    auto pf_v = [&](int ch, int buf) {
        uint32_t sdst = sb + VB_B + buf * 8192;
        const fp16* src = vh_g + (size_t)(ch * 64) * 64;
        #pragma unroll
        for (int t = 0; t < 2; t++) {
            int j = tid + 256 * t;
            int row = j >> 3, kg = j & 7;
            CP_ASYNC16(sdst + (uint32_t)(row * 128 + ((kg ^ (row & 7)) << 4)),
                       src + (size_t)row * 64 + kg * 8);
        }
    };
    {
        int row = tid >> 3, kg = tid & 7;
        uint32_t so = (uint32_t)(row * 128 + ((kg ^ (row & 7)) << 4));
        CP_ASYNC16(sb + PB_B + so,        qh_g + (size_t)row * 64 + kg * 8);
        CP_ASYNC16(sb + PB_B + 4096 + so, ql_g + (size_t)row * 64 + kg * 8);
    }
    pf_k(0, 0);
    CP_COMMIT();

    // ---- scores: per-warp (q-half, key-quarter) tensor-core mapping ----
    int qh16 = (w >> 2) * 16;
    int keyq = w & 3;
    int matA = lane >> 3;
    int arow = qh16 + ((matA & 1) << 3) + (lane & 7);
    int akg = matA >> 1;
    uint32_t offQ[4];
    #pragma unroll
    for (int ks = 0; ks < 4; ks++)
        offQ[ks] = (uint32_t)(arow * 128 + (((ks * 2 + akg) ^ (arow & 7)) << 4));
    int brow = keyq * 16 + ((matA >> 1) << 3) + (lane & 7);
    int bkg = matA & 1;
    uint32_t offK[4];
    #pragma unroll
    for (int ks = 0; ks < 4; ks++)
        offK[ks] = (uint32_t)(brow * 128 + (((ks * 2 + bkg) ^ (brow & 7)) << 4));

    const uint32_t qhb = sb + PB_B, qlb = sb + PB_B + 4096;

    for (int ch = 0; ch < 8; ch++) {
        if (ch < 7) pf_k(ch + 1, (ch + 1) & 1);
        CP_COMMIT();
        CP_WAIT1();
        __syncthreads();
        uint32_t kb = sb + PB_B + 8192 + (ch & 1) * 8192;

        float c0[4] = {0.f,0.f,0.f,0.f}, c1[4] = {0.f,0.f,0.f,0.f};
        #pragma unroll
        for (int ks = 0; ks < 4; ks++) {
            uint32_t ah[4], al[4], bbv[4];
            LDSM_X4(ah[0], ah[1], ah[2], ah[3], qhb + offQ[ks]);
            LDSM_X4(al[0], al[1], al[2], al[3], qlb + offQ[ks]);
            LDSM_X4(bbv[0], bbv[1], bbv[2], bbv[3], kb + offK[ks]);
            MMA_F16(c0, ah, bbv[0], bbv[1]);
            MMA_F16(c0, al, bbv[0], bbv[1]);
            MMA_F16(c1, ah, bbv[2], bbv[3]);
            MMA_F16(c1, al, bbv[2], bbv[3]);
        }
        int tc = lane >> 2, tcol = (lane & 3) * 2;
        int q0 = qh16 + tc, q1 = q0 + 8;
        #pragma unroll
        for (int nt = 0; nt < 2; nt++) {
            float* cc = nt ? c1 : c0;
            int key0 = ch * 64 + keyq * 16 + nt * 8 + tcol;
            bool m0 = (tb[key0] == 0), m1 = (tb[key0 + 1] == 0);
            sc[q0 * 513 + key0]     = m0 ? -INFINITY : cc[0] * 0.125f;
            sc[q0 * 513 + key0 + 1] = m1 ? -INFINITY : cc[1] * 0.125f;
            sc[q1 * 513 + key0]     = m0 ? -INFINITY : cc[2] * 0.125f;
            sc[q1 * 513 + key0 + 1] = m1 ? -INFINITY : cc[3] * 0.125f;
        }
        __syncthreads();
    }

    // prefetch V chunk 0 (region distinct from Q/K and Pb)
    pf_v(0, 0); CP_COMMIT();

    // ---- softmax: 8 warps x 4 rows; writes probs (fp32) + Pb (fp16, A-layout chunks) ----
    #pragma unroll 1
    for (int rr = 0; rr < 4; rr++) {
        int row = w * 4 + rr;
        float* srow = sc + row * 513;
        float m = -INFINITY;
        for (int j = lane; j < 512; j += 32) m = fmaxf(m, srow[j]);
        #pragma unroll
        for (int o = 16; o > 0; o >>= 1) m = fmaxf(m, __shfl_xor_sync(~0u, m, o));
        float sum = 0.f;
        for (int j = lane; j < 512; j += 32) {
            float e = __expf(srow[j] - m);
            srow[j] = e; sum += e;
        }
        #pragma unroll
        for (int o = 16; o > 0; o >>= 1) sum += __shfl_xor_sync(~0u, sum, o);
        float inv = 1.f / sum;
        float* prow = probs + ((((size_t)b * HH + h) * SS + qb * 32 + row) << 9);
        for (int j = lane; j < 512; j += 32) {
            float p = srow[j] * inv;
            prow[j] = p;
            int chnk = j >> 6, col = j & 63;
            uint32_t pa = sb + PB_B + chnk * 4096 +
                          (uint32_t)(row * 128 + (((col >> 3) ^ (row & 7)) << 4) + (col & 7) * 2);
            fp16 pv = __float2half_rn(p);
            asm volatile("st.shared.u16 [%0], %1;" :: "r"(pa), "h"(__half_as_ushort(pv)) : "memory");
        }
    }

    // ---- AV via tensor cores: warp = (q-half, d-quarter) ----
    int qhalf = w & 1, dq = w >> 1;
    int arl = ((matA & 1) << 3) + (lane & 7);
    int akb = matA >> 1;
    uint32_t offPA[4];
    #pragma unroll
    for (int ks = 0; ks < 4; ks++) {
        int row = qhalf * 16 + arl;
        offPA[ks] = (uint32_t)(row * 128 + (((ks * 2 + akb) ^ (row & 7)) << 4));
    }
    int krl = ((matA & 1) << 3) + (lane & 7);
    int nsel = matA >> 1;
    uint32_t offVB[4];
    #pragma unroll
    for (int ks = 0; ks < 4; ks++) {
        int row = ks * 16 + krl;
        offVB[ks] = (uint32_t)(row * 128 + (((dq * 2 + nsel) ^ (row & 7)) << 4));
    }

    float accV[2][4];
    #pragma unroll
    for (int i = 0; i < 2; i++)
        #pragma unroll
        for (int qq = 0; qq < 4; qq++) accV[i][qq] = 0.f;

    for (int ch = 0; ch < 8; ch++) {
        CP_WAIT0();
        __syncthreads();           // chunk ch V ready; also orders Pb stores (ch=0)
        if (ch < 7) { pf_v(ch + 1, (ch + 1) & 1); CP_COMMIT(); }
        uint32_t Vb = sb + VB_B + (ch & 1) * 8192;
        uint32_t Pc = sb + PB_B + ch * 4096;
        #pragma unroll
        for (int ks = 0; ks < 4; ks++) {
            uint32_t pa[4], v0, v1, v2, v3;
            LDSM_X4(pa[0], pa[1], pa[2], pa[3], Pc + offPA[ks]);
            LDSM_X4_T(v0, v1, v2, v3, Vb + offVB[ks]);
            MMA_F16(accV[0], pa, v0, v1);
            MMA_F16(accV[1], pa, v2, v3);
        }
    }

    // write av [B,S,H*64] fp16
    int tc2 = lane >> 2, tcol2 = (lane & 3) * 2;
    int qrow0 = qb * 32 + qhalf * 16 + tc2;
    int qrow1 = qrow0 + 8;
    #pragma unroll
    for (int nt = 0; nt < 2; nt++) {
        int d = dq * 16 + nt * 8 + tcol2;
        size_t o0 = (((size_t)(b * SS + qrow0)) << 10) + h * 64 + d;
        size_t o1 = (((size_t)(b * SS + qrow1)) << 10) + h * 64 + d;
        *(__half2*)(avh + o0) = __halves2half2(__float2half_rn(accV[nt][0]), __float2half_rn(accV[nt][1]));
        *(__half2*)(avh + o1) = __halves2half2(__float2half_rn(accV[nt][2]), __float2half_rn(accV[nt][3]));
    }
}

// ======== layernorm of (p0 + p1 + res + bias), fp16 out ========
__global__ __launch_bounds__(256)
void ln_sum_kernel(const float* __restrict__ p0, const float* __restrict__ p1,
                   const float* __restrict__ res, const float* __restrict__ bias,
                   float* __restrict__ out, fp16* __restrict__ oh)
{
    int row = blockIdx.x;
    int tid = threadIdx.x;
    size_t base = (size_t)row * DD;
    float v0 = p0[base + tid]       + p1[base + tid]       + res[base + tid]       + bias[tid];
    float v1 = p0[base + tid + 256] + p1[base + tid + 256] + res[base + tid + 256] + bias[tid + 256];
    float v2 = p0[base + tid + 512] + p1[base + tid + 512] + res[base + tid + 512] + bias[tid + 512];
    float v3 = p0[base + tid + 768] + p1[base + tid + 768] + res[base + tid + 768] + bias[tid + 768];
    float s = v0 + v1 + v2 + v3;

    __shared__ float sh[32];
    #pragma unroll
    for (int o = 16; o > 0; o >>= 1) s += __shfl_down_sync(~0u, s, o);
    if ((tid & 31) == 0) sh[tid >> 5] = s;
    __syncthreads();
    if (tid < 8) {
        s = sh[tid];
        #pragma unroll
        for (int o = 4; o > 0; o >>= 1) s += __shfl_down_sync(0xffu, s, o);
        if (tid == 0) sh[0] = s;
    }
    __syncthreads();
    float mean = sh[0] * (1.f / 1024.f);
    float d0 = v0 - mean, d1 = v1 - mean, d2 = v2 - mean, d3 = v3 - mean;
    float qv = d0*d0 + d1*d1 + d2*d2 + d3*d3;
    __syncthreads();
    #pragma unroll
    for (int o = 16; o > 0; o >>= 1) qv += __shfl_down_sync(~0u, qv, o);
    if ((tid & 31) == 0) sh[tid >> 5] = qv;
    __syncthreads();
    if (tid < 8) {
        qv = sh[tid];
        #pragma unroll
        for (int o = 4; o > 0; o >>= 1) qv += __shfl_down_sync(0xffu, qv, o);
        if (tid == 0) sh[0] = qv;
    }
    __syncthreads();
    float inv = rsqrtf(sh[0] * (1.f / 1024.f) + 1e-5f);
    #pragma unroll
    for (int jj = 0; jj < 4; jj++) {
        float d = (jj == 0 ? d0 : jj == 1 ? d1 : jj == 2 ? d2 : d3);
        float val = d * inv;
        int idx = tid + jj * 256;
        out[base + idx] = val;
        oh[base + idx] = __float2half_rn(val);
    }
}

// ================= host driver =================
extern "C" void kernel_launch(void* const* d_in, const int* in_sizes, int n_in,
                              void* d_out, int out_size)
{
    const int*   tok = (const int*)d_in[0];
    const float* we  = (const float*)d_in[1];
    const float* pt  = (const float*)d_in[2];
    const float* Wq  = (const float*)d_in[3];  const float* bq = (const float*)d_in[4];
    const float* Wk  = (const float*)d_in[5];  const float* bk = (const float*)d_in[6];
    const float* Wv  = (const float*)d_in[7];  const float* bv = (const float*)d_in[8];
    const float* Wo  = (const float*)d_in[9];  const float* bo = (const float*)d_in[10];
    const float* W1  = (const float*)d_in[11]; const float* b1 = (const float*)d_in[12];
    const float* W2  = (const float*)d_in[13]; const float* b2 = (const float*)d_in[14];
    float* out = (float*)d_out;

    float *x, *x1p, *bqkv, *part;
    fp16 *xh, *qhp, *qlp, *khp, *vhp, *avh, *x1h, *ffh;
    cudaGetSymbolAddress((void**)&x,   g_x);
    cudaGetSymbolAddress((void**)&xh,  g_xh);
    cudaGetSymbolAddress((void**)&qhp, g_qh);  cudaGetSymbolAddress((void**)&qlp, g_ql);
    cudaGetSymbolAddress((void**)&khp, g_kh);  cudaGetSymbolAddress((void**)&vhp, g_vh);
    cudaGetSymbolAddress((void**)&avh, g_avh);
    cudaGetSymbolAddress((void**)&x1p, g_x1);
    cudaGetSymbolAddress((void**)&x1h, g_x1h);
    cudaGetSymbolAddress((void**)&ffh, g_ffh);
    cudaGetSymbolAddress((void**)&part, g_part);
    cudaGetSymbolAddress((void**)&bqkv, g_bqkv);

    fp16 *wqkvT, *woT, *w1T, *w2T;
    cudaGetSymbolAddress((void**)&wqkvT, g_wqkvT);
    cudaGetSymbolAddress((void**)&woT, g_woT);
    cudaGetSymbolAddress((void**)&w1T, g_w1T);
    cudaGetSymbolAddress((void**)&w2T, g_w2T);

    const int GSMEM = 3 * (64 * 128 + 128 * 128);   // 73728
    cudaFuncSetAttribute(gemm_kernel, cudaFuncAttributeMaxDynamicSharedMemorySize, GSMEM);
    cudaFuncSetAttribute(attn_kernel, cudaFuncAttributeMaxDynamicSharedMemorySize, ATT_SMEM);

    static cudaStream_t s2 = nullptr;
    static cudaEvent_t eFork = nullptr, eLay[LL];
    if (!s2) {
        cudaStreamCreate(&s2);
        cudaEventCreateWithFlags(&eFork, cudaEventDisableTiming);
        for (int l = 0; l < LL; l++) cudaEventCreateWithFlags(&eLay[l], cudaEventDisableTiming);
    }

    const size_t PROJ = (size_t)DD * DD;
    const size_t WQKV = (size_t)LL * DD * DD;
    const size_t W1SZ = (size_t)DD * DFF;
    const size_t W2SZ = (size_t)DFF * DD;
    const size_t CORR = (size_t)BB * HH * SS * SS;
    const size_t PSZ  = (size_t)MTOK * DD;

    auto split_layer = [&](int l, cudaStream_t st) {
        dim3 gP(DD/32, DD/32);
        wsplit_kernel<<<gP, 256, 0, st>>>(Wq + l*PROJ, wqkvT + l*PROJ,          DD, DD);
        wsplit_kernel<<<gP, 256, 0, st>>>(Wk + l*PROJ, wqkvT + WQKV + l*PROJ,   DD, DD);
        wsplit_kernel<<<gP, 256, 0, st>>>(Wv + l*PROJ, wqkvT + 2*WQKV + l*PROJ, DD, DD);
        wsplit_kernel<<<gP, 256, 0, st>>>(Wo + l*PROJ, woT + l*PROJ, DD, DD);
        dim3 g1(DFF/32, DD/32);
        wsplit_kernel<<<g1, 256, 0, st>>>(W1 + l*W1SZ, w1T + l*W1SZ, DD, DFF);
        dim3 g2(DD/32, DFF/32);
        wsplit_kernel<<<g2, 256, 0, st>>>(W2 + l*W2SZ, w2T + l*W2SZ, DFF, DD);
    };

    bcat_kernel<<<(LL*DD + 255)/256, 256>>>(bq, bk, bv, bqkv, LL*DD);
    split_layer(0, (cudaStream_t)0);
    embed_kernel<<<MTOK, 256>>>(tok, we, pt, x, xh);

    cudaEventRecord(eFork, (cudaStream_t)0);
    cudaStreamWaitEvent(s2, eFork, 0);
    for (int l = 1; l < LL; l++) {
        split_layer(l, s2);
        cudaEventRecord(eLay[l], s2);
    }

    dim3 gQKV(DD / 128, MTOK / 64, 3);    // 768 CTAs
    dim3 gFF (DFF / 128, MTOK / 64);      // 1024 CTAs
    dim3 gSK (DD / 128, MTOK / 64, 2);    // 512 CTAs (split-K2)
    dim3 gA  (SS / 32, HH, BB);           // (16,16,4)

    for (int l = 0; l < LL; l++) {
        if (l > 0) cudaStreamWaitEvent((cudaStream_t)0, eLay[l], 0);

        gemm_kernel<<<gQKV, 256, GSMEM>>>(xh, wqkvT + l*PROJ,
                                          bqkv + l*DD, nullptr, qhp, qlp, khp, vhp,
                                          DD, DD, DD, 3, WQKV, (size_t)LL*DD);

        float* probs_l = out + (size_t)MTOK * DD + (size_t)l * CORR;
        attn_kernel<<<gA, 256, ATT_SMEM>>>(qhp, qlp, khp, vhp, tok, probs_l, avh);

        // O-proj: split-K2 partials, then fused sum+res+bias+LN
        gemm_kernel<<<gSK, 256, GSMEM>>>(avh, woT + l*PROJ, bo + l*DD,
                                         part, nullptr, nullptr, nullptr, nullptr,
                                         DD/2, DD, DD, 4, 0, 0);
        ln_sum_kernel<<<MTOK, 256>>>(part, part + PSZ, x, bo + l*DD, x1p, x1h);

        gemm_kernel<<<gFF, 256, GSMEM>>>(x1h, w1T + l*W1SZ, b1 + l*DFF,
                                         nullptr, ffh, nullptr, nullptr, nullptr,
                                         DD, DD, DFF, 1, 0, 0);

        // FFN2: split-K2 partials, then fused sum+res+bias+LN
        gemm_kernel<<<gSK, 256, GSMEM>>>(ffh, w2T + l*W2SZ, b2 + l*DD,
                                         part, nullptr, nullptr, nullptr, nullptr,
                                         DFF/2, DFF, DD, 4, 0, 0);
        float* xdst = (l == LL - 1) ? out : x;
        ln_sum_kernel<<<MTOK, 256>>>(part, part + PSZ, x1p, b2 + l*DD, xdst, xh);
    }
}